// round 8
// baseline (speedup 1.0000x reference)
#include <cuda_runtime.h>
#include <cuda_fp16.h>

// Problem constants (from reference)
#define L_DIM  12
#define BS_DIM 2048          // B*S = 8*256
#define D_DIM  1024
#define N_DIM  2048
#define K_DIM  5
#define INV_TEMP 10.0f       // 1 / 0.1
#define EPS2 (1e-8f * 1e-8f)

#define ITEMS (L_DIM * N_DIM)            // 24576
#define ROWS_TOTAL (L_DIM * BS_DIM)      // 24576 rows of 1024 floats
#define FINAL_SCALE (-1.0f / (float)(L_DIM * N_DIM))
#define NROWS 6                          // pos + 5 negatives

// Normalized fp16 activations: ROWS_TOTAL x 1024 halfs = 48 MB.
// Stored as uint4 (8 halfs each): row = 128 uint4.
__device__ uint4 g_norm16[(size_t)ROWS_TOTAL * (D_DIM / 8)];

__global__ void mi_zero_kernel(float* out) { *out = 0.0f; }

__device__ __forceinline__ float warp_allreduce(float v) {
    #pragma unroll
    for (int o = 16; o; o >>= 1) v += __shfl_xor_sync(0xFFFFFFFFu, v, o);
    return v;
}

// ---------------- Prepass: normalize rows, write fp16 ----------------
// One warp per row. Pass 1: sum of squares (8 float4/lane). Pass 2: re-read
// (L1-hot), scale, pack to fp16, write one uint4/lane per step.
__global__ void __launch_bounds__(256, 8)
mi_norm_kernel(const float* __restrict__ act)
{
    const int warp = threadIdx.x >> 5;
    const int lane = threadIdx.x & 31;
    const int row  = blockIdx.x * 8 + warp;   // 3072 blocks x 8 warps

    const float4* __restrict__ src = (const float4*)act + (size_t)row * 256;

    float sq = 0.0f;
    #pragma unroll
    for (int j = 0; j < 8; j++) {
        const float4 v = __ldg(&src[lane + j * 32]);
        sq += v.x * v.x + v.y * v.y + v.z * v.z + v.w * v.w;
    }
    sq = warp_allreduce(sq);
    const float inv = rsqrtf(fmaxf(sq, EPS2));   // == 1/max(||x||, eps)

    uint4* dst = g_norm16 + (size_t)row * 128;
    #pragma unroll
    for (int jj = 0; jj < 4; jj++) {
        const int f = 2 * (lane + jj * 32);      // float4 index (covers 8 floats)
        const float4 v0 = __ldg(&src[f]);
        const float4 v1 = __ldg(&src[f + 1]);
        const __half2 h0 = __floats2half2_rn(v0.x * inv, v0.y * inv);
        const __half2 h1 = __floats2half2_rn(v0.z * inv, v0.w * inv);
        const __half2 h2 = __floats2half2_rn(v1.x * inv, v1.y * inv);
        const __half2 h3 = __floats2half2_rn(v1.z * inv, v1.w * inv);
        uint4 o;
        o.x = reinterpret_cast<const unsigned&>(h0);
        o.y = reinterpret_cast<const unsigned&>(h1);
        o.z = reinterpret_cast<const unsigned&>(h2);
        o.w = reinterpret_cast<const unsigned&>(h3);
        dst[lane + jj * 32] = o;
    }
}

// ---------------- Main: gather normalized fp16 rows, dot only ----------------
// One warp per (l, n) item. 4 j-steps x 7 uint4 loads (8 halfs each).
#define MAIN_WARPS 4
__global__ void __launch_bounds__(MAIN_WARPS * 32, 8)
mi_loss_kernel(const int* __restrict__ aidx,
               const int* __restrict__ pidx,
               const int* __restrict__ nidx,
               float* __restrict__ out)
{
    const int warp = threadIdx.x >> 5;
    const int lane = threadIdx.x & 31;
    const int item = blockIdx.x * MAIN_WARPS + warp;
    const int l = item >> 11;
    const int n = item & (N_DIM - 1);

    const uint4* __restrict__ sp = g_norm16;
    const unsigned lbase = (unsigned)(l * BS_DIM);

    unsigned aoff = (lbase + (unsigned)__ldg(&aidx[n])) * 128u + lane;
    unsigned roff[NROWS];
    roff[0] = (lbase + (unsigned)__ldg(&pidx[n])) * 128u + lane;
    #pragma unroll
    for (int k = 0; k < K_DIM; k++)
        roff[1 + k] = (lbase + (unsigned)__ldg(&nidx[n * K_DIM + k])) * 128u + lane;

    float dot[NROWS];
    #pragma unroll
    for (int r = 0; r < NROWS; r++) dot[r] = 0.0f;

    #pragma unroll 1
    for (int j = 0; j < 4; j++) {
        const uint4 au = __ldg(&sp[aoff]);
        uint4 vu[NROWS];
        #pragma unroll
        for (int r = 0; r < NROWS; r++) vu[r] = __ldg(&sp[roff[r]]);

        aoff += 32;
        #pragma unroll
        for (int r = 0; r < NROWS; r++) roff[r] += 32;

        const float2 a0 = __half22float2(reinterpret_cast<const __half2&>(au.x));
        const float2 a1 = __half22float2(reinterpret_cast<const __half2&>(au.y));
        const float2 a2 = __half22float2(reinterpret_cast<const __half2&>(au.z));
        const float2 a3 = __half22float2(reinterpret_cast<const __half2&>(au.w));

        #pragma unroll
        for (int r = 0; r < NROWS; r++) {
            const float2 b0 = __half22float2(reinterpret_cast<const __half2&>(vu[r].x));
            const float2 b1 = __half22float2(reinterpret_cast<const __half2&>(vu[r].y));
            const float2 b2 = __half22float2(reinterpret_cast<const __half2&>(vu[r].z));
            const float2 b3 = __half22float2(reinterpret_cast<const __half2&>(vu[r].w));
            dot[r] += a0.x * b0.x + a0.y * b0.y
                    + a1.x * b1.x + a1.y * b1.y
                    + a2.x * b2.x + a2.y * b2.y
                    + a3.x * b3.x + a3.y * b3.y;
        }
    }

    #pragma unroll
    for (int r = 0; r < NROWS; r++) dot[r] = warp_allreduce(dot[r]);

    const float pos_sim = dot[0] * INV_TEMP;
    float negsum = 0.0f;
    #pragma unroll
    for (int r = 1; r < NROWS; r++) negsum += expf(dot[r] * INV_TEMP);

    const float loss = pos_sim - logf(expf(pos_sim) + negsum);

    __shared__ float s_loss[MAIN_WARPS];
    if (lane == 0) s_loss[warp] = loss;
    __syncthreads();
    if (threadIdx.x == 0) {
        float t = 0.0f;
        #pragma unroll
        for (int w = 0; w < MAIN_WARPS; w++) t += s_loss[w];
        atomicAdd(out, t * FINAL_SCALE);
    }
}

extern "C" void kernel_launch(void* const* d_in, const int* in_sizes, int n_in,
                              void* d_out, int out_size)
{
    const float* act  = (const float*)d_in[0];
    const int*   aidx = (const int*)d_in[1];
    const int*   pidx = (const int*)d_in[2];
    const int*   nidx = (const int*)d_in[3];
    float* out = (float*)d_out;

    mi_zero_kernel<<<1, 1>>>(out);
    mi_norm_kernel<<<ROWS_TOTAL / 8, 256>>>(act);
    mi_loss_kernel<<<ITEMS / MAIN_WARPS, MAIN_WARPS * 32>>>(aidx, pidx, nidx, out);
}

// round 10
// speedup vs baseline: 1.0793x; 1.0793x over previous
#include <cuda_runtime.h>
#include <cuda_fp16.h>

// Problem constants (from reference)
#define L_DIM  12
#define BS_DIM 2048          // B*S = 8*256
#define D_DIM  1024
#define N_DIM  2048
#define K_DIM  5
#define INV_TEMP 10.0f       // 1 / 0.1
#define EPS2 (1e-8f * 1e-8f)

#define ITEMS (L_DIM * N_DIM)            // 24576
#define ROWS_TOTAL (L_DIM * BS_DIM)      // 24576 rows of 1024 floats
#define FINAL_SCALE (-1.0f / (float)(L_DIM * N_DIM))
#define NROWS 6                          // pos + 5 negatives

// Normalized fp16 activations: ROWS_TOTAL x 1024 halfs = 48 MB.
// Row layout: 128 uint4 (8 halfs each); written as 256 uint2 (half of a uint4).
__device__ uint4 g_norm16[(size_t)ROWS_TOTAL * (D_DIM / 8)];

__device__ __forceinline__ float warp_allreduce(float v) {
    #pragma unroll
    for (int o = 16; o; o >>= 1) v += __shfl_xor_sync(0xFFFFFFFFu, v, o);
    return v;
}

// ---------------- Prepass: normalize rows -> fp16, single read ----------------
// One warp per row. Row kept in registers (8 float4/lane); after the norm
// reduction, scale + pack + store 8 coalesced STG.64. Also zeroes *out.
__global__ void __launch_bounds__(256)
mi_norm_kernel(const float* __restrict__ act, float* __restrict__ out)
{
    if (blockIdx.x == 0 && threadIdx.x == 0) *out = 0.0f;

    const int warp = threadIdx.x >> 5;
    const int lane = threadIdx.x & 31;
    const int row  = blockIdx.x * 8 + warp;   // 3072 blocks x 8 warps

    const float4* __restrict__ src = (const float4*)act + (size_t)row * 256;

    float4 v[8];
    float sq = 0.0f;
    #pragma unroll
    for (int j = 0; j < 8; j++) {
        v[j] = __ldg(&src[lane + j * 32]);
        sq += v[j].x * v[j].x + v[j].y * v[j].y
            + v[j].z * v[j].z + v[j].w * v[j].w;
    }
    sq = warp_allreduce(sq);
    const float inv = rsqrtf(fmaxf(sq, EPS2));   // == 1/max(||x||, eps)

    // Store as uint2 (4 halfs) at the same float4-granular position:
    // element range covered by lane+j*32 is identical for src and dst.
    uint2* __restrict__ dst = (uint2*)(g_norm16 + (size_t)row * 128);
    #pragma unroll
    for (int j = 0; j < 8; j++) {
        const __half2 h0 = __floats2half2_rn(v[j].x * inv, v[j].y * inv);
        const __half2 h1 = __floats2half2_rn(v[j].z * inv, v[j].w * inv);
        uint2 o;
        o.x = reinterpret_cast<const unsigned&>(h0);
        o.y = reinterpret_cast<const unsigned&>(h1);
        dst[lane + j * 32] = o;
    }
}

// ---------------- Main: gather normalized fp16 rows, dot only ----------------
// One warp per (l, n) item. 4 j-steps x 7 uint4 loads (8 halfs each).
#define MAIN_WARPS 8
__global__ void __launch_bounds__(MAIN_WARPS * 32, 5)
mi_loss_kernel(const int* __restrict__ aidx,
               const int* __restrict__ pidx,
               const int* __restrict__ nidx,
               float* __restrict__ out)
{
    const int warp = threadIdx.x >> 5;
    const int lane = threadIdx.x & 31;
    const int item = blockIdx.x * MAIN_WARPS + warp;
    const int l = item >> 11;
    const int n = item & (N_DIM - 1);

    const uint4* __restrict__ sp = g_norm16;
    const unsigned lbase = (unsigned)(l * BS_DIM);

    unsigned aoff = (lbase + (unsigned)__ldg(&aidx[n])) * 128u + lane;
    unsigned roff[NROWS];
    roff[0] = (lbase + (unsigned)__ldg(&pidx[n])) * 128u + lane;
    #pragma unroll
    for (int k = 0; k < K_DIM; k++)
        roff[1 + k] = (lbase + (unsigned)__ldg(&nidx[n * K_DIM + k])) * 128u + lane;

    float dot[NROWS];
    #pragma unroll
    for (int r = 0; r < NROWS; r++) dot[r] = 0.0f;

    #pragma unroll 1
    for (int j = 0; j < 4; j++) {
        const uint4 au = __ldg(&sp[aoff]);
        uint4 vu[NROWS];
        #pragma unroll
        for (int r = 0; r < NROWS; r++) vu[r] = __ldg(&sp[roff[r]]);

        aoff += 32;
        #pragma unroll
        for (int r = 0; r < NROWS; r++) roff[r] += 32;

        const float2 a0 = __half22float2(reinterpret_cast<const __half2&>(au.x));
        const float2 a1 = __half22float2(reinterpret_cast<const __half2&>(au.y));
        const float2 a2 = __half22float2(reinterpret_cast<const __half2&>(au.z));
        const float2 a3 = __half22float2(reinterpret_cast<const __half2&>(au.w));

        #pragma unroll
        for (int r = 0; r < NROWS; r++) {
            const float2 b0 = __half22float2(reinterpret_cast<const __half2&>(vu[r].x));
            const float2 b1 = __half22float2(reinterpret_cast<const __half2&>(vu[r].y));
            const float2 b2 = __half22float2(reinterpret_cast<const __half2&>(vu[r].z));
            const float2 b3 = __half22float2(reinterpret_cast<const __half2&>(vu[r].w));
            dot[r] += a0.x * b0.x + a0.y * b0.y
                    + a1.x * b1.x + a1.y * b1.y
                    + a2.x * b2.x + a2.y * b2.y
                    + a3.x * b3.x + a3.y * b3.y;
        }
    }

    #pragma unroll
    for (int r = 0; r < NROWS; r++) dot[r] = warp_allreduce(dot[r]);

    const float pos_sim = dot[0] * INV_TEMP;
    float negsum = 0.0f;
    #pragma unroll
    for (int r = 1; r < NROWS; r++) negsum += expf(dot[r] * INV_TEMP);

    const float loss = pos_sim - logf(expf(pos_sim) + negsum);

    __shared__ float s_loss[MAIN_WARPS];
    if (lane == 0) s_loss[warp] = loss;
    __syncthreads();
    if (threadIdx.x == 0) {
        float t = 0.0f;
        #pragma unroll
        for (int w = 0; w < MAIN_WARPS; w++) t += s_loss[w];
        atomicAdd(out, t * FINAL_SCALE);
    }
}

extern "C" void kernel_launch(void* const* d_in, const int* in_sizes, int n_in,
                              void* d_out, int out_size)
{
    const float* act  = (const float*)d_in[0];
    const int*   aidx = (const int*)d_in[1];
    const int*   pidx = (const int*)d_in[2];
    const int*   nidx = (const int*)d_in[3];
    float* out = (float*)d_out;

    mi_norm_kernel<<<ROWS_TOTAL / 8, 256>>>(act, out);
    mi_loss_kernel<<<ITEMS / MAIN_WARPS, MAIN_WARPS * 32>>>(aidx, pidx, nidx, out);
}

// round 11
// speedup vs baseline: 1.1731x; 1.0869x over previous
#include <cuda_runtime.h>
#include <cuda_fp16.h>

// Problem constants (from reference)
#define L_DIM  12
#define BS_DIM 2048          // B*S = 8*256
#define D_DIM  1024
#define N_DIM  2048
#define K_DIM  5
#define INV_TEMP 10.0f       // 1 / 0.1
#define EPS2 (1e-8f * 1e-8f)

#define ITEMS (L_DIM * N_DIM)            // 24576
#define ROWS_TOTAL (L_DIM * BS_DIM)      // 24576 rows of 1024 floats
#define FINAL_SCALE (-1.0f / (float)(L_DIM * N_DIM))
#define NROWS 6                          // pos + 5 negatives

// Normalized fp16 activations: ROWS_TOTAL x 1024 halfs = 48 MB.
__device__ uint4 g_norm16[(size_t)ROWS_TOTAL * (D_DIM / 8)];

__device__ __forceinline__ float warp_allreduce(float v) {
    #pragma unroll
    for (int o = 16; o; o >>= 1) v += __shfl_xor_sync(0xFFFFFFFFu, v, o);
    return v;
}

// ---------------- Prepass: normalize rows -> fp16, single read ----------------
// One warp per row; row held in registers. Near DRAM roofline — unchanged.
__global__ void __launch_bounds__(256)
mi_norm_kernel(const float* __restrict__ act, float* __restrict__ out)
{
    if (blockIdx.x == 0 && threadIdx.x == 0) *out = 0.0f;

    const int warp = threadIdx.x >> 5;
    const int lane = threadIdx.x & 31;
    const int row  = blockIdx.x * 8 + warp;   // 3072 blocks x 8 warps

    const float4* __restrict__ src = (const float4*)act + (size_t)row * 256;

    float4 v[8];
    float sq = 0.0f;
    #pragma unroll
    for (int j = 0; j < 8; j++) {
        v[j] = __ldg(&src[lane + j * 32]);
        sq += v[j].x * v[j].x + v[j].y * v[j].y
            + v[j].z * v[j].z + v[j].w * v[j].w;
    }
    sq = warp_allreduce(sq);
    const float inv = rsqrtf(fmaxf(sq, EPS2));   // == 1/max(||x||, eps)

    uint2* __restrict__ dst = (uint2*)(g_norm16 + (size_t)row * 128);
    #pragma unroll
    for (int j = 0; j < 8; j++) {
        const __half2 h0 = __floats2half2_rn(v[j].x * inv, v[j].y * inv);
        const __half2 h1 = __floats2half2_rn(v[j].z * inv, v[j].w * inv);
        uint2 o;
        o.x = reinterpret_cast<const unsigned&>(h0);
        o.y = reinterpret_cast<const unsigned&>(h1);
        dst[lane + j * 32] = o;
    }
}

// ---------------- Main: gather fp16 rows, HFMA2 dot ----------------
// One warp per (l, n) item. 4 j-steps x 7 uint4 loads; accumulation stays in
// half2 (4 HFMA2 per row per step), converted to fp32 once at the end.
#define MAIN_WARPS 8
__global__ void __launch_bounds__(MAIN_WARPS * 32, 5)
mi_loss_kernel(const int* __restrict__ aidx,
               const int* __restrict__ pidx,
               const int* __restrict__ nidx,
               float* __restrict__ out)
{
    const int warp = threadIdx.x >> 5;
    const int lane = threadIdx.x & 31;
    const int item = blockIdx.x * MAIN_WARPS + warp;
    const int l = item >> 11;
    const int n = item & (N_DIM - 1);

    const uint4* __restrict__ sp = g_norm16;
    const unsigned lbase = (unsigned)(l * BS_DIM);

    unsigned aoff = (lbase + (unsigned)__ldg(&aidx[n])) * 128u + lane;
    unsigned roff[NROWS];
    roff[0] = (lbase + (unsigned)__ldg(&pidx[n])) * 128u + lane;
    #pragma unroll
    for (int k = 0; k < K_DIM; k++)
        roff[1 + k] = (lbase + (unsigned)__ldg(&nidx[n * K_DIM + k])) * 128u + lane;

    __half2 acc[NROWS];
    #pragma unroll
    for (int r = 0; r < NROWS; r++)
        acc[r] = __floats2half2_rn(0.0f, 0.0f);

    #pragma unroll 1
    for (int j = 0; j < 4; j++) {
        const uint4 au = __ldg(&sp[aoff]);
        uint4 vu[NROWS];
        #pragma unroll
        for (int r = 0; r < NROWS; r++) vu[r] = __ldg(&sp[roff[r]]);

        aoff += 32;
        #pragma unroll
        for (int r = 0; r < NROWS; r++) roff[r] += 32;

        const __half2 a0 = reinterpret_cast<const __half2&>(au.x);
        const __half2 a1 = reinterpret_cast<const __half2&>(au.y);
        const __half2 a2 = reinterpret_cast<const __half2&>(au.z);
        const __half2 a3 = reinterpret_cast<const __half2&>(au.w);

        #pragma unroll
        for (int r = 0; r < NROWS; r++) {
            acc[r] = __hfma2(a0, reinterpret_cast<const __half2&>(vu[r].x), acc[r]);
            acc[r] = __hfma2(a1, reinterpret_cast<const __half2&>(vu[r].y), acc[r]);
            acc[r] = __hfma2(a2, reinterpret_cast<const __half2&>(vu[r].z), acc[r]);
            acc[r] = __hfma2(a3, reinterpret_cast<const __half2&>(vu[r].w), acc[r]);
        }
    }

    float dot[NROWS];
    #pragma unroll
    for (int r = 0; r < NROWS; r++) {
        const float2 f = __half22float2(acc[r]);
        dot[r] = warp_allreduce(f.x + f.y);
    }

    const float pos_sim = dot[0] * INV_TEMP;
    float negsum = 0.0f;
    #pragma unroll
    for (int r = 1; r < NROWS; r++) negsum += expf(dot[r] * INV_TEMP);

    const float loss = pos_sim - logf(expf(pos_sim) + negsum);

    __shared__ float s_loss[MAIN_WARPS];
    if (lane == 0) s_loss[warp] = loss;
    __syncthreads();
    if (threadIdx.x == 0) {
        float t = 0.0f;
        #pragma unroll
        for (int w = 0; w < MAIN_WARPS; w++) t += s_loss[w];
        atomicAdd(out, t * FINAL_SCALE);
    }
}

extern "C" void kernel_launch(void* const* d_in, const int* in_sizes, int n_in,
                              void* d_out, int out_size)
{
    const float* act  = (const float*)d_in[0];
    const int*   aidx = (const int*)d_in[1];
    const int*   pidx = (const int*)d_in[2];
    const int*   nidx = (const int*)d_in[3];
    float* out = (float*)d_out;

    mi_norm_kernel<<<ROWS_TOTAL / 8, 256>>>(act, out);
    mi_loss_kernel<<<ITEMS / MAIN_WARPS, MAIN_WARPS * 32>>>(aidx, pidx, nidx, out);
}